// round 14
// baseline (speedup 1.0000x reference)
#include <cuda_runtime.h>
#include <cuda_bf16.h>
#include <cuda_fp16.h>
#include <cstdint>

#define B_  4096
#define T_  256
#define D_  20
#define E_  64
#define H_  16
#define G4_ 64
#define TGRP 32
#define SGROW 80

__device__ __half g_G[(size_t)B_ * G4_ * T_];
__device__ float g_hf[B_ * H_];
__device__ __align__(16) unsigned char g_WfH[9216];
__device__ __align__(16) unsigned char g_WfL[9216];
__device__ __align__(16) unsigned char g_W0H[5120];
__device__ __align__(16) unsigned char g_W0L[5120];

typedef unsigned long long u64;

__device__ __forceinline__ float tanha(float x){ float y; asm("tanh.approx.f32 %0,%1;":"=f"(y):"f"(x)); return y; }
__device__ __forceinline__ u64 pack2(float a,float b){ u64 r; asm("mov.b64 %0,{%1,%2};":"=l"(r):"f"(a),"f"(b)); return r; }
__device__ __forceinline__ void unpack2(u64 v,float&a,float&b){ asm("mov.b64 {%0,%1},%2;":"=f"(a),"=f"(b):"l"(v)); }
__device__ __forceinline__ u64 fma2(u64 a,u64 b,u64 c){ u64 d; asm("fma.rn.f32x2 %0,%1,%2,%3;":"=l"(d):"l"(a),"l"(b),"l"(c)); return d; }
__device__ __forceinline__ u64 add2(u64 a,u64 b){ u64 d; asm("add.rn.f32x2 %0,%1,%2;":"=l"(d):"l"(a),"l"(b)); return d; }
__device__ __forceinline__ uint32_t smem_u32(const void* p){
    uint32_t a; asm("{ .reg .u64 t; cvta.to.shared.u64 t, %1; cvt.u32.u64 %0, t; }":"=r"(a):"l"(p)); return a;
}
__device__ __forceinline__ void mma16816(float& c0, float& c1, float& c2, float& c3,
                                         uint32_t a0, uint32_t a1, uint32_t a2, uint32_t a3,
                                         uint32_t b0, uint32_t b1){
    asm volatile("mma.sync.aligned.m16n8k16.row.col.f32.bf16.bf16.f32 "
        "{%0,%1,%2,%3}, {%4,%5,%6,%7}, {%8,%9}, {%0,%1,%2,%3};"
        : "+f"(c0),"+f"(c1),"+f"(c2),"+f"(c3)
        : "r"(a0),"r"(a1),"r"(a2),"r"(a3),"r"(b0),"r"(b1));
}
__device__ __forceinline__ void ldm4(uint32_t& r0, uint32_t& r1, uint32_t& r2, uint32_t& r3, uint32_t a){
    asm volatile("ldmatrix.sync.aligned.m8n8.x4.shared.b16 {%0,%1,%2,%3}, [%4];"
        : "=r"(r0),"=r"(r1),"=r"(r2),"=r"(r3) : "r"(a));
}
__device__ __forceinline__ void split2(u64 p, uint32_t& hi, uint32_t& lo){
    float v0, v1; unpack2(p, v0, v1);
    v0 = fmaxf(v0, 0.f); v1 = fmaxf(v1, 0.f);
    __nv_bfloat16 h0 = __float2bfloat16(v0), h1 = __float2bfloat16(v1);
    __nv_bfloat16 l0 = __float2bfloat16(v0 - __bfloat162float(h0));
    __nv_bfloat16 l1 = __float2bfloat16(v1 - __bfloat162float(h1));
    hi = (uint32_t)__bfloat16_as_ushort(h0) | ((uint32_t)__bfloat16_as_ushort(h1) << 16);
    lo = (uint32_t)__bfloat16_as_ushort(l0) | ((uint32_t)__bfloat16_as_ushort(l1) << 16);
}
__device__ __forceinline__ void split2nr(float v0, float v1, uint32_t& hi, uint32_t& lo){
    __nv_bfloat16 h0 = __float2bfloat16(v0), h1 = __float2bfloat16(v1);
    __nv_bfloat16 l0 = __float2bfloat16(v0 - __bfloat162float(h0));
    __nv_bfloat16 l1 = __float2bfloat16(v1 - __bfloat162float(h1));
    hi = (uint32_t)__bfloat16_as_ushort(h0) | ((uint32_t)__bfloat16_as_ushort(h1) << 16);
    lo = (uint32_t)__bfloat16_as_ushort(l0) | ((uint32_t)__bfloat16_as_ushort(l1) << 16);
}

#define OAH   0u
#define OAL   36864u
#define OWH   73728u
#define OWL   82944u
#define OW0H  92160u
#define OW0L  97280u
#define OB0   102400u
#define OBF   102656u
#define SMEM1 102912u

// ---------------- Prepack (R13-exact) ----------------
__global__ void k_prep(const float* __restrict__ Wf, const float* __restrict__ W0)
{
    int i = blockIdx.x * 256 + threadIdx.x;
    if (i < 4096) {
        int k = i >> 6, c = i & 63;
        float v = Wf[i];
        __nv_bfloat16 h = __float2bfloat16(v);
        __nv_bfloat16 l = __float2bfloat16(v - __bfloat162float(h));
        *(unsigned short*)(g_WfH + c * 144 + k * 2) = __bfloat16_as_ushort(h);
        *(unsigned short*)(g_WfL + c * 144 + k * 2) = __bfloat16_as_ushort(l);
        if (i < 64) {
            *(uint4*)(g_WfH + i * 144 + 128) = make_uint4(0,0,0,0);
            *(uint4*)(g_WfL + i * 144 + 128) = make_uint4(0,0,0,0);
        }
    }
    int j = i - 4096;
    if (j >= 0 && j < 2048) {
        int k = j >> 6, c = j & 63;
        float v = (k < D_) ? W0[k * 64 + c] : 0.f;
        __nv_bfloat16 h = __float2bfloat16(v);
        __nv_bfloat16 l = __float2bfloat16(v - __bfloat162float(h));
        *(unsigned short*)(g_W0H + c * 80 + k * 2) = __bfloat16_as_ushort(h);
        *(unsigned short*)(g_W0L + c * 80 + k * 2) = __bfloat16_as_ushort(l);
        if (j < 64) {
            *(uint4*)(g_W0H + j * 80 + 64) = make_uint4(0,0,0,0);
            *(uint4*)(g_W0L + j * 80 + 64) = make_uint4(0,0,0,0);
        }
    }
}

// ---------------- Phase 1 (R13-exact) ----------------
__global__ void __launch_bounds__(256, 2) k_phase1(
    const float* __restrict__ x, const float* __restrict__ b0,
    const float* __restrict__ bf)
{
    extern __shared__ char sm[];
    const uint32_t sb = smem_u32(sm);
    float* b0s = (float*)(sm + OB0);
    float* bfs = (float*)(sm + OBF);

    const int tid = threadIdx.x, wid = tid >> 5, lane = tid & 31;
    const int b = blockIdx.x;

    if (tid < 64) { b0s[tid] = b0[tid]; bfs[tid] = bf[tid]; }
    {
        const uint4* srcH = (const uint4*)g_WfH;
        const uint4* srcL = (const uint4*)g_WfL;
        #pragma unroll
        for (int q = 0; q < 3; q++) {
            int i = tid + q * 256;
            if (i < 576) {
                *(uint4*)(sm + OWH + i * 16) = srcH[i];
                *(uint4*)(sm + OWL + i * 16) = srcL[i];
            }
        }
        const uint4* s0H = (const uint4*)g_W0H;
        const uint4* s0L = (const uint4*)g_W0L;
        #pragma unroll
        for (int q = 0; q < 2; q++) {
            int i = tid + q * 256;
            if (i < 320) {
                *(uint4*)(sm + OW0H + i * 16) = s0H[i];
                *(uint4*)(sm + OW0L + i * 16) = s0L[i];
            }
        }
    }

    {
        const int t = tid;
        const float4* xp4 = (const float4*)(x + (size_t)b * (T_ * D_) + t * D_);
        float xv[20];
        #pragma unroll
        for (int q = 0; q < 5; q++) {
            float4 f = __ldg(xp4 + q);
            xv[4*q] = f.x; xv[4*q+1] = f.y; xv[4*q+2] = f.z; xv[4*q+3] = f.w;
        }
        uint32_t hw[16], lw[16];
        #pragma unroll
        for (int p = 0; p < 10; p++) split2nr(xv[2*p], xv[2*p+1], hw[p], lw[p]);
        #pragma unroll
        for (int p = 10; p < 16; p++) { hw[p] = 0u; lw[p] = 0u; }
        #pragma unroll
        for (int q = 0; q < 4; q++) {
            *(uint4*)(sm + OAH + t * 144 + q * 16) = make_uint4(hw[4*q], hw[4*q+1], hw[4*q+2], hw[4*q+3]);
            *(uint4*)(sm + OAL + t * 144 + q * 16) = make_uint4(lw[4*q], lw[4*q+1], lw[4*q+2], lw[4*q+3]);
        }
    }
    __syncthreads();

    const int t0 = wid * 32;
    const int arow = ((lane >> 3) & 1) * 8 + (lane & 7);
    const int acol = (lane >> 4) * 16;
    const int cb = (lane & 3) * 2;

    float acc1[2][8][4];
    #pragma unroll
    for (int nt = 0; nt < 8; nt++) {
        float2 bv = *(float2*)&b0s[nt * 8 + cb];
        #pragma unroll
        for (int m = 0; m < 2; m++) {
            acc1[m][nt][0] = bv.x; acc1[m][nt][1] = bv.y;
            acc1[m][nt][2] = bv.x; acc1[m][nt][3] = bv.y;
        }
    }
    #pragma unroll
    for (int ks = 0; ks < 2; ks++) {
        const int k0 = ks * 16;
        uint32_t Ah[2][4], Al[2][4];
        #pragma unroll
        for (int mt = 0; mt < 2; mt++) {
            uint32_t ad = sb + OAH + (uint32_t)(t0 + mt * 16 + arow) * 144 + (uint32_t)(k0 * 2 + acol);
            ldm4(Ah[mt][0], Ah[mt][1], Ah[mt][2], Ah[mt][3], ad);
            ldm4(Al[mt][0], Al[mt][1], Al[mt][2], Al[mt][3], ad + (OAL - OAH));
        }
        #pragma unroll
        for (int nt = 0; nt < 8; nt++) {
            const uint32_t boff = (uint32_t)((nt * 8 + (lane >> 2)) * 80 + k0 * 2 + (lane & 3) * 4);
            uint32_t bh0 = *(const uint32_t*)(sm + OW0H + boff);
            uint32_t bh1 = *(const uint32_t*)(sm + OW0H + boff + 16);
            uint32_t bl0 = *(const uint32_t*)(sm + OW0L + boff);
            uint32_t bl1 = *(const uint32_t*)(sm + OW0L + boff + 16);
            #pragma unroll
            for (int mt = 0; mt < 2; mt++) {
                mma16816(acc1[mt][nt][0], acc1[mt][nt][1], acc1[mt][nt][2], acc1[mt][nt][3],
                         Ah[mt][0], Ah[mt][1], Ah[mt][2], Ah[mt][3], bh0, bh1);
                mma16816(acc1[mt][nt][0], acc1[mt][nt][1], acc1[mt][nt][2], acc1[mt][nt][3],
                         Ah[mt][0], Ah[mt][1], Ah[mt][2], Ah[mt][3], bl0, bl1);
                mma16816(acc1[mt][nt][0], acc1[mt][nt][1], acc1[mt][nt][2], acc1[mt][nt][3],
                         Al[mt][0], Al[mt][1], Al[mt][2], Al[mt][3], bh0, bh1);
            }
        }
    }
    __syncthreads();

    #pragma unroll
    for (int mt = 0; mt < 2; mt++) {
        const int r0 = t0 + mt * 16 + (lane >> 2);
        #pragma unroll
        for (int nt = 0; nt < 8; nt++) {
            const int c = nt * 8 + cb;
            uint32_t h0, l0, h1, l1;
            split2(pack2(acc1[mt][nt][0], acc1[mt][nt][1]), h0, l0);
            split2(pack2(acc1[mt][nt][2], acc1[mt][nt][3]), h1, l1);
            *(uint32_t*)(sm + OAH + r0 * 144 + c * 2)       = h0;
            *(uint32_t*)(sm + OAL + r0 * 144 + c * 2)       = l0;
            *(uint32_t*)(sm + OAH + (r0 + 8) * 144 + c * 2) = h1;
            *(uint32_t*)(sm + OAL + (r0 + 8) * 144 + c * 2) = l1;
        }
    }
    __syncthreads();

    float acc[2][8][4];
    #pragma unroll
    for (int nt = 0; nt < 8; nt++) {
        float2 bv = *(float2*)&bfs[nt * 8 + cb];
        #pragma unroll
        for (int m = 0; m < 2; m++) {
            acc[m][nt][0] = bv.x; acc[m][nt][1] = bv.y;
            acc[m][nt][2] = bv.x; acc[m][nt][3] = bv.y;
        }
    }
    #pragma unroll
    for (int ks = 0; ks < 4; ks++) {
        const int k0 = ks * 16;
        uint32_t Ah[2][4], Al[2][4];
        #pragma unroll
        for (int mt = 0; mt < 2; mt++) {
            uint32_t ad = sb + OAH + (uint32_t)(t0 + mt * 16 + arow) * 144 + (uint32_t)(k0 * 2 + acol);
            ldm4(Ah[mt][0], Ah[mt][1], Ah[mt][2], Ah[mt][3], ad);
            ldm4(Al[mt][0], Al[mt][1], Al[mt][2], Al[mt][3], ad + (OAL - OAH));
        }
        #pragma unroll
        for (int nt = 0; nt < 8; nt++) {
            const uint32_t boff = (uint32_t)((nt * 8 + (lane >> 2)) * 144 + k0 * 2 + (lane & 3) * 4);
            uint32_t bh0 = *(const uint32_t*)(sm + OWH + boff);
            uint32_t bh1 = *(const uint32_t*)(sm + OWH + boff + 16);
            uint32_t bl0 = *(const uint32_t*)(sm + OWL + boff);
            uint32_t bl1 = *(const uint32_t*)(sm + OWL + boff + 16);
            #pragma unroll
            for (int mt = 0; mt < 2; mt++) {
                mma16816(acc[mt][nt][0], acc[mt][nt][1], acc[mt][nt][2], acc[mt][nt][3],
                         Ah[mt][0], Ah[mt][1], Ah[mt][2], Ah[mt][3], bh0, bh1);
                mma16816(acc[mt][nt][0], acc[mt][nt][1], acc[mt][nt][2], acc[mt][nt][3],
                         Ah[mt][0], Ah[mt][1], Ah[mt][2], Ah[mt][3], bl0, bl1);
                mma16816(acc[mt][nt][0], acc[mt][nt][1], acc[mt][nt][2], acc[mt][nt][3],
                         Al[mt][0], Al[mt][1], Al[mt][2], Al[mt][3], bh0, bh1);
            }
        }
    }

    {
        __half* Gb = g_G + (size_t)b * (G4_ * T_);
        #pragma unroll
        for (int mt = 0; mt < 2; mt++) {
            const int t = t0 + mt * 16 + (lane >> 2);
            #pragma unroll
            for (int nt = 0; nt < 8; nt++) {
                const int c = nt * 8 + cb;
                *(__half2*)&Gb[(size_t)t * 64 + c]       = __floats2half2_rn(acc[mt][nt][0], acc[mt][nt][1]);
                *(__half2*)&Gb[(size_t)(t + 8) * 64 + c] = __floats2half2_rn(acc[mt][nt][2], acc[mt][nt][3]);
            }
        }
    }
}

// ---------------- Phase 2: scan, SMEM duplicated-pair h broadcast ----------------
__global__ void __launch_bounds__(128) k_scan(const float* __restrict__ Wf)
{
    __shared__ float sg[4][2][8 * SGROW];
    __shared__ __align__(16) float2 hsh[4][16];

    const int tid = threadIdx.x, w = tid >> 5, l = tid & 31;
    const int b = blockIdx.x * 4 + w;
    const int j = l & 15;
    const int cA = (l < 16) ? l : (32 + j);
    const int cB = cA + 16;
    const int offA = cA + ((cA >> 5) << 4);
    const int offB = cB + ((cB >> 5) << 4);

    u64 wp[16];
    #pragma unroll
    for (int k = 0; k < 16; k++)
        wp[k] = pack2(Wf[(E_ + k) * G4_ + cA], Wf[(E_ + k) * G4_ + cB]);

    const __half* Gb = g_G + (size_t)b * (G4_ * T_);

    int soff[2][2];
    #pragma unroll
    for (int k = 0; k < 2; k++) {
        int f  = l + 32 * k;
        int ti = f >> 3;
        int c4a = (f & 7) * 2;
        soff[k][0] = ti * SGROW + c4a * 4 + ((c4a >> 3) << 4);
        int c4b = c4a + 1;
        soff[k][1] = ti * SGROW + c4b * 4 + ((c4b >> 3) << 4);
    }

    float h = 0.f, c = 0.f;
    if (l < 16) hsh[w][l] = make_float2(0.f, 0.f);

    float bU, kV, aV, bV;
    if (l < 16) { bU = 0.f;  kV = 1.f;  aV = 1.f;  bV = 0.f;  }
    else        { bU = 0.5f; kV = 0.5f; aV = 0.5f; bV = 0.5f; }

    uint4 r[2];
    {
        const uint4* src = (const uint4*)Gb;
        #pragma unroll
        for (int k = 0; k < 2; k++) r[k] = src[l + 32 * k];
        #pragma unroll
        for (int k = 0; k < 2; k++) {
            const __half2* hp2 = (const __half2*)&r[k];
            float2 f0 = __half22float2(hp2[0]);
            float2 f1 = __half22float2(hp2[1]);
            float2 f2 = __half22float2(hp2[2]);
            float2 f3 = __half22float2(hp2[3]);
            *(float4*)&sg[w][0][soff[k][0]] = make_float4(f0.x, f0.y, f1.x, f1.y);
            *(float4*)&sg[w][0][soff[k][1]] = make_float4(f2.x, f2.y, f3.x, f3.y);
        }
    }
    __syncwarp();

    for (int tg = 0; tg < TGRP; ++tg) {
        const int buf = tg & 1;
        if (tg < TGRP - 1) {
            const uint4* src = (const uint4*)(Gb + (size_t)(tg + 1) * 512);
            #pragma unroll
            for (int k = 0; k < 2; k++) r[k] = src[l + 32 * k];
        }
        const float* sgb = &sg[w][buf][0];
        #pragma unroll
        for (int i = 0; i < 8; i++) {
            float ga = sgb[i * SGROW + offA];
            float gb = sgb[i * SGROW + offB];
            const ulonglong2* hp = (const ulonglong2*)&hsh[w][0];
            ulonglong2 h01 = hp[0], h23 = hp[1], h45 = hp[2], h67 = hp[3];
            ulonglong2 h89 = hp[4], hab = hp[5], hcd = hp[6], hef = hp[7];
            u64 a0p = pack2(ga, gb);
            a0p = fma2(h01.x, wp[0],  a0p); a0p = fma2(h01.y, wp[1],  a0p);
            a0p = fma2(h23.x, wp[2],  a0p); a0p = fma2(h23.y, wp[3],  a0p);
            u64 a1p = fma2(h45.x, wp[4], 0ULL); a1p = fma2(h45.y, wp[5],  a1p);
            a1p = fma2(h67.x, wp[6],  a1p); a1p = fma2(h67.y, wp[7],  a1p);
            u64 a2p = fma2(h89.x, wp[8], 0ULL); a2p = fma2(h89.y, wp[9],  a2p);
            a2p = fma2(hab.x, wp[10], a2p); a2p = fma2(hab.y, wp[11], a2p);
            u64 a3p = fma2(hcd.x, wp[12], 0ULL); a3p = fma2(hcd.y, wp[13], a3p);
            a3p = fma2(hef.x, wp[14], a3p); a3p = fma2(hef.y, wp[15], a3p);
            u64 acc = add2(add2(a0p, a1p), add2(a2p, a3p));
            float xA, xB; unpack2(acc, xA, xB);

            float u = fmaf(0.5f, tanha(fmaf(0.5f, xA, bU)), 0.5f);
            float v = fmaf(aV, tanha(kV * xB), bV);
            float sf = __shfl_down_sync(0xffffffffu, u, 16);   // converges warp (reads done)
            float so = __shfl_down_sync(0xffffffffu, v, 16);
            if (l < 16) {
                c = fmaf(sf, c, u * v);
                h = so * tanha(c);
                hsh[w][l] = make_float2(h, h);
            }
            __syncwarp();
        }
        if (tg < TGRP - 1) {
            #pragma unroll
            for (int k = 0; k < 2; k++) {
                const __half2* hp2 = (const __half2*)&r[k];
                float2 f0 = __half22float2(hp2[0]);
                float2 f1 = __half22float2(hp2[1]);
                float2 f2 = __half22float2(hp2[2]);
                float2 f3 = __half22float2(hp2[3]);
                *(float4*)&sg[w][buf ^ 1][soff[k][0]] = make_float4(f0.x, f0.y, f1.x, f1.y);
                *(float4*)&sg[w][buf ^ 1][soff[k][1]] = make_float4(f2.x, f2.y, f3.x, f3.y);
            }
            __syncwarp();
        }
    }
    if (l < 16) g_hf[b * H_ + l] = h;
}

// ---------------- Tail: 4 rows per warp (grid/4), weights amortized ----------------
__global__ void __launch_bounds__(256) k_tail(
    const float* __restrict__ x, const float* __restrict__ W0,
    const float* __restrict__ b0, const float* __restrict__ Wb,
    const float* __restrict__ bb,
    const float* __restrict__ W1, const float* __restrict__ b1,
    const float* __restrict__ W2, const float* __restrict__ b2,
    const float* __restrict__ W3, const float* __restrict__ b3,
    float* __restrict__ out)
{
    __shared__ float W0s[D_ * E_];
    __shared__ float Wbs[E_ * G4_];
    __shared__ float b0s[64], bbs[64];
    __shared__ float W1s[32 * 64], W2s[64 * 16], W3s[32];
    __shared__ float b1s[64], b2s[16], b3s[2];
    __shared__ float xsh[8][20];
    __shared__ __align__(16) float2 hes[8][64];
    __shared__ float hbs[8][16];
    __shared__ float insh[8][32], ush[8][64], vsh[8][16];

    const int tid = threadIdx.x, w = tid >> 5, l = tid & 31;

    for (int i = tid; i < D_ * E_;  i += 256) W0s[i] = W0[i];
    for (int i = tid; i < E_ * G4_; i += 256) Wbs[i] = Wb[i];
    for (int i = tid; i < 32 * 64;  i += 256) W1s[i] = W1[i];
    for (int i = tid; i < 64 * 16;  i += 256) W2s[i] = W2[i];
    if (tid < 32) W3s[tid] = W3[tid];
    if (tid < 64) { b0s[tid] = b0[tid]; bbs[tid] = bb[tid]; b1s[tid] = b1[tid]; }
    if (tid < 16) b2s[tid] = b2[tid];
    if (tid < 2)  b3s[tid] = b3[tid];
    __syncthreads();

    const int j = l & 15;
    const int cA = (l < 16) ? l : (32 + j);
    const int cB = cA + 16;
    float bU, kV, aV, bV;
    if (l < 16) { bU = 0.f;  kV = 1.f;  aV = 1.f;  bV = 0.f;  }
    else        { bU = 0.5f; kV = 0.5f; aV = 0.5f; bV = 0.5f; }

    #pragma unroll
    for (int rr = 0; rr < 4; rr++) {
        const int b = blockIdx.x * 32 + w * 4 + rr;

        if (l < 20) xsh[w][l] = x[((size_t)b * T_ + (T_ - 1)) * D_ + l];
        __syncwarp();

        float a0 = b0s[l], a1 = b0s[l + 32];
        #pragma unroll
        for (int d = 0; d < D_; d++) {
            float xv = xsh[w][d];
            a0 = fmaf(xv, W0s[d * E_ + l],      a0);
            a1 = fmaf(xv, W0s[d * E_ + l + 32], a1);
        }
        a0 = fmaxf(a0, 0.f); a1 = fmaxf(a1, 0.f);
        hes[w][l]      = make_float2(a0, a0);
        hes[w][l + 32] = make_float2(a1, a1);
        __syncwarp();

        u64 acc = pack2(bbs[cA], bbs[cB]);
        #pragma unroll 8
        for (int k = 0; k < E_; k++) {
            u64 hd = *(const u64*)&hes[w][k];
            acc = fma2(hd, pack2(Wbs[k * G4_ + cA], Wbs[k * G4_ + cB]), acc);
        }
        float xA, xB; unpack2(acc, xA, xB);

        float u = fmaf(0.5f, tanha(fmaf(0.5f, xA, bU)), 0.5f);
        float v = fmaf(aV, tanha(kV * xB), bV);
        float so = __shfl_down_sync(0xffffffffu, v, 16);
        if (l < 16) {
            float cc = u * v;
            hbs[w][l] = so * tanha(cc);
        }
        __syncwarp();

        insh[w][l] = (l < 16) ? g_hf[b * H_ + l] : hbs[w][l - 16];
        __syncwarp();

        float u0 = b1s[l], u1 = b1s[l + 32];
        #pragma unroll 8
        for (int k = 0; k < 32; k++) {
            float t = insh[w][k];
            u0 = fmaf(t, W1s[k * 64 + l],      u0);
            u1 = fmaf(t, W1s[k * 64 + l + 32], u1);
        }
        ush[w][l]      = fmaxf(u0, 0.f);
        ush[w][l + 32] = fmaxf(u1, 0.f);
        __syncwarp();

        if (l < 16) {
            float a = b2s[l];
            #pragma unroll 8
            for (int k = 0; k < 64; k++) a = fmaf(ush[w][k], W2s[k * 16 + l], a);
            vsh[w][l] = fmaxf(a, 0.f);
        }
        __syncwarp();

        if (l < 2) {
            float a = b3s[l];
            #pragma unroll
            for (int k = 0; k < 16; k++) a = fmaf(vsh[w][k], W3s[k * 2 + l], a);
            out[b * 2 + l] = a;
        }
        __syncwarp();
    }
}

extern "C" void kernel_launch(void* const* d_in, const int* in_sizes, int n_in,
                              void* d_out, int out_size)
{
    (void)in_sizes; (void)n_in; (void)out_size;
    const float* x  = (const float*)d_in[0];
    const float* W0 = (const float*)d_in[1];
    const float* b0 = (const float*)d_in[2];
    const float* Wf = (const float*)d_in[3];
    const float* bf = (const float*)d_in[4];
    const float* Wb = (const float*)d_in[5];
    const float* bb = (const float*)d_in[6];
    const float* W1 = (const float*)d_in[7];
    const float* b1 = (const float*)d_in[8];
    const float* W2 = (const float*)d_in[9];
    const float* b2 = (const float*)d_in[10];
    const float* W3 = (const float*)d_in[11];
    const float* b3 = (const float*)d_in[12];
    float* out = (float*)d_out;

    cudaFuncSetAttribute(k_phase1, cudaFuncAttributeMaxDynamicSharedMemorySize, (int)SMEM1);

    k_prep  <<<24, 256>>>(Wf, W0);
    k_phase1<<<B_,      256, SMEM1>>>(x, b0, bf);
    k_scan  <<<B_ / 4,  128>>>(Wf);
    k_tail  <<<B_ / 32, 256>>>(x, W0, b0, Wb, bb, W1, b1, W2, b2, W3, b3, out);
}

// round 15
// speedup vs baseline: 1.7364x; 1.7364x over previous
#include <cuda_runtime.h>
#include <cuda_bf16.h>
#include <cuda_fp16.h>
#include <cstdint>

#define B_  4096
#define T_  256
#define D_  20
#define E_  64
#define H_  16
#define G4_ 64
#define TGRP 32
#define SGROW 80

__device__ __half g_G[(size_t)B_ * G4_ * T_];
__device__ float g_hf[B_ * H_];
__device__ __align__(16) unsigned char g_WfH[9216];
__device__ __align__(16) unsigned char g_WfL[9216];
__device__ __align__(16) unsigned char g_W0H[5120];
__device__ __align__(16) unsigned char g_W0L[5120];

typedef unsigned long long u64;

__device__ __forceinline__ float tanha(float x){ float y; asm("tanh.approx.f32 %0,%1;":"=f"(y):"f"(x)); return y; }
__device__ __forceinline__ u64 pack2(float a,float b){ u64 r; asm("mov.b64 %0,{%1,%2};":"=l"(r):"f"(a),"f"(b)); return r; }
__device__ __forceinline__ void unpack2(u64 v,float&a,float&b){ asm("mov.b64 {%0,%1},%2;":"=f"(a),"=f"(b):"l"(v)); }
__device__ __forceinline__ u64 fma2(u64 a,u64 b,u64 c){ u64 d; asm("fma.rn.f32x2 %0,%1,%2,%3;":"=l"(d):"l"(a),"l"(b),"l"(c)); return d; }
__device__ __forceinline__ u64 add2(u64 a,u64 b){ u64 d; asm("add.rn.f32x2 %0,%1,%2;":"=l"(d):"l"(a),"l"(b)); return d; }
__device__ __forceinline__ uint32_t smem_u32(const void* p){
    uint32_t a; asm("{ .reg .u64 t; cvta.to.shared.u64 t, %1; cvt.u32.u64 %0, t; }":"=r"(a):"l"(p)); return a;
}
__device__ __forceinline__ void mma16816(float& c0, float& c1, float& c2, float& c3,
                                         uint32_t a0, uint32_t a1, uint32_t a2, uint32_t a3,
                                         uint32_t b0, uint32_t b1){
    asm volatile("mma.sync.aligned.m16n8k16.row.col.f32.bf16.bf16.f32 "
        "{%0,%1,%2,%3}, {%4,%5,%6,%7}, {%8,%9}, {%0,%1,%2,%3};"
        : "+f"(c0),"+f"(c1),"+f"(c2),"+f"(c3)
        : "r"(a0),"r"(a1),"r"(a2),"r"(a3),"r"(b0),"r"(b1));
}
__device__ __forceinline__ void ldm4(uint32_t& r0, uint32_t& r1, uint32_t& r2, uint32_t& r3, uint32_t a){
    asm volatile("ldmatrix.sync.aligned.m8n8.x4.shared.b16 {%0,%1,%2,%3}, [%4];"
        : "=r"(r0),"=r"(r1),"=r"(r2),"=r"(r3) : "r"(a));
}
__device__ __forceinline__ void split2(u64 p, uint32_t& hi, uint32_t& lo){
    float v0, v1; unpack2(p, v0, v1);
    v0 = fmaxf(v0, 0.f); v1 = fmaxf(v1, 0.f);
    __nv_bfloat16 h0 = __float2bfloat16(v0), h1 = __float2bfloat16(v1);
    __nv_bfloat16 l0 = __float2bfloat16(v0 - __bfloat162float(h0));
    __nv_bfloat16 l1 = __float2bfloat16(v1 - __bfloat162float(h1));
    hi = (uint32_t)__bfloat16_as_ushort(h0) | ((uint32_t)__bfloat16_as_ushort(h1) << 16);
    lo = (uint32_t)__bfloat16_as_ushort(l0) | ((uint32_t)__bfloat16_as_ushort(l1) << 16);
}
__device__ __forceinline__ void split2nr(float v0, float v1, uint32_t& hi, uint32_t& lo){
    __nv_bfloat16 h0 = __float2bfloat16(v0), h1 = __float2bfloat16(v1);
    __nv_bfloat16 l0 = __float2bfloat16(v0 - __bfloat162float(h0));
    __nv_bfloat16 l1 = __float2bfloat16(v1 - __bfloat162float(h1));
    hi = (uint32_t)__bfloat16_as_ushort(h0) | ((uint32_t)__bfloat16_as_ushort(h1) << 16);
    lo = (uint32_t)__bfloat16_as_ushort(l0) | ((uint32_t)__bfloat16_as_ushort(l1) << 16);
}

#define OAH   0u
#define OAL   36864u
#define OWH   73728u
#define OWL   82944u
#define OW0H  92160u
#define OW0L  97280u
#define OB0   102400u
#define OBF   102656u
#define SMEM1 102912u

// ---------------- Prepack (R13-exact) ----------------
__global__ void k_prep(const float* __restrict__ Wf, const float* __restrict__ W0)
{
    int i = blockIdx.x * 256 + threadIdx.x;
    if (i < 4096) {
        int k = i >> 6, c = i & 63;
        float v = Wf[i];
        __nv_bfloat16 h = __float2bfloat16(v);
        __nv_bfloat16 l = __float2bfloat16(v - __bfloat162float(h));
        *(unsigned short*)(g_WfH + c * 144 + k * 2) = __bfloat16_as_ushort(h);
        *(unsigned short*)(g_WfL + c * 144 + k * 2) = __bfloat16_as_ushort(l);
        if (i < 64) {
            *(uint4*)(g_WfH + i * 144 + 128) = make_uint4(0,0,0,0);
            *(uint4*)(g_WfL + i * 144 + 128) = make_uint4(0,0,0,0);
        }
    }
    int j = i - 4096;
    if (j >= 0 && j < 2048) {
        int k = j >> 6, c = j & 63;
        float v = (k < D_) ? W0[k * 64 + c] : 0.f;
        __nv_bfloat16 h = __float2bfloat16(v);
        __nv_bfloat16 l = __float2bfloat16(v - __bfloat162float(h));
        *(unsigned short*)(g_W0H + c * 80 + k * 2) = __bfloat16_as_ushort(h);
        *(unsigned short*)(g_W0L + c * 80 + k * 2) = __bfloat16_as_ushort(l);
        if (j < 64) {
            *(uint4*)(g_W0H + j * 80 + 64) = make_uint4(0,0,0,0);
            *(uint4*)(g_W0L + j * 80 + 64) = make_uint4(0,0,0,0);
        }
    }
}

// ---------------- Phase 1 (R13-exact) ----------------
__global__ void __launch_bounds__(256, 2) k_phase1(
    const float* __restrict__ x, const float* __restrict__ b0,
    const float* __restrict__ bf)
{
    extern __shared__ char sm[];
    const uint32_t sb = smem_u32(sm);
    float* b0s = (float*)(sm + OB0);
    float* bfs = (float*)(sm + OBF);

    const int tid = threadIdx.x, wid = tid >> 5, lane = tid & 31;
    const int b = blockIdx.x;

    if (tid < 64) { b0s[tid] = b0[tid]; bfs[tid] = bf[tid]; }
    {
        const uint4* srcH = (const uint4*)g_WfH;
        const uint4* srcL = (const uint4*)g_WfL;
        #pragma unroll
        for (int q = 0; q < 3; q++) {
            int i = tid + q * 256;
            if (i < 576) {
                *(uint4*)(sm + OWH + i * 16) = srcH[i];
                *(uint4*)(sm + OWL + i * 16) = srcL[i];
            }
        }
        const uint4* s0H = (const uint4*)g_W0H;
        const uint4* s0L = (const uint4*)g_W0L;
        #pragma unroll
        for (int q = 0; q < 2; q++) {
            int i = tid + q * 256;
            if (i < 320) {
                *(uint4*)(sm + OW0H + i * 16) = s0H[i];
                *(uint4*)(sm + OW0L + i * 16) = s0L[i];
            }
        }
    }

    {
        const int t = tid;
        const float4* xp4 = (const float4*)(x + (size_t)b * (T_ * D_) + t * D_);
        float xv[20];
        #pragma unroll
        for (int q = 0; q < 5; q++) {
            float4 f = __ldg(xp4 + q);
            xv[4*q] = f.x; xv[4*q+1] = f.y; xv[4*q+2] = f.z; xv[4*q+3] = f.w;
        }
        uint32_t hw[16], lw[16];
        #pragma unroll
        for (int p = 0; p < 10; p++) split2nr(xv[2*p], xv[2*p+1], hw[p], lw[p]);
        #pragma unroll
        for (int p = 10; p < 16; p++) { hw[p] = 0u; lw[p] = 0u; }
        #pragma unroll
        for (int q = 0; q < 4; q++) {
            *(uint4*)(sm + OAH + t * 144 + q * 16) = make_uint4(hw[4*q], hw[4*q+1], hw[4*q+2], hw[4*q+3]);
            *(uint4*)(sm + OAL + t * 144 + q * 16) = make_uint4(lw[4*q], lw[4*q+1], lw[4*q+2], lw[4*q+3]);
        }
    }
    __syncthreads();

    const int t0 = wid * 32;
    const int arow = ((lane >> 3) & 1) * 8 + (lane & 7);
    const int acol = (lane >> 4) * 16;
    const int cb = (lane & 3) * 2;

    float acc1[2][8][4];
    #pragma unroll
    for (int nt = 0; nt < 8; nt++) {
        float2 bv = *(float2*)&b0s[nt * 8 + cb];
        #pragma unroll
        for (int m = 0; m < 2; m++) {
            acc1[m][nt][0] = bv.x; acc1[m][nt][1] = bv.y;
            acc1[m][nt][2] = bv.x; acc1[m][nt][3] = bv.y;
        }
    }
    #pragma unroll
    for (int ks = 0; ks < 2; ks++) {
        const int k0 = ks * 16;
        uint32_t Ah[2][4], Al[2][4];
        #pragma unroll
        for (int mt = 0; mt < 2; mt++) {
            uint32_t ad = sb + OAH + (uint32_t)(t0 + mt * 16 + arow) * 144 + (uint32_t)(k0 * 2 + acol);
            ldm4(Ah[mt][0], Ah[mt][1], Ah[mt][2], Ah[mt][3], ad);
            ldm4(Al[mt][0], Al[mt][1], Al[mt][2], Al[mt][3], ad + (OAL - OAH));
        }
        #pragma unroll
        for (int nt = 0; nt < 8; nt++) {
            const uint32_t boff = (uint32_t)((nt * 8 + (lane >> 2)) * 80 + k0 * 2 + (lane & 3) * 4);
            uint32_t bh0 = *(const uint32_t*)(sm + OW0H + boff);
            uint32_t bh1 = *(const uint32_t*)(sm + OW0H + boff + 16);
            uint32_t bl0 = *(const uint32_t*)(sm + OW0L + boff);
            uint32_t bl1 = *(const uint32_t*)(sm + OW0L + boff + 16);
            #pragma unroll
            for (int mt = 0; mt < 2; mt++) {
                mma16816(acc1[mt][nt][0], acc1[mt][nt][1], acc1[mt][nt][2], acc1[mt][nt][3],
                         Ah[mt][0], Ah[mt][1], Ah[mt][2], Ah[mt][3], bh0, bh1);
                mma16816(acc1[mt][nt][0], acc1[mt][nt][1], acc1[mt][nt][2], acc1[mt][nt][3],
                         Ah[mt][0], Ah[mt][1], Ah[mt][2], Ah[mt][3], bl0, bl1);
                mma16816(acc1[mt][nt][0], acc1[mt][nt][1], acc1[mt][nt][2], acc1[mt][nt][3],
                         Al[mt][0], Al[mt][1], Al[mt][2], Al[mt][3], bh0, bh1);
            }
        }
    }
    __syncthreads();

    #pragma unroll
    for (int mt = 0; mt < 2; mt++) {
        const int r0 = t0 + mt * 16 + (lane >> 2);
        #pragma unroll
        for (int nt = 0; nt < 8; nt++) {
            const int c = nt * 8 + cb;
            uint32_t h0, l0, h1, l1;
            split2(pack2(acc1[mt][nt][0], acc1[mt][nt][1]), h0, l0);
            split2(pack2(acc1[mt][nt][2], acc1[mt][nt][3]), h1, l1);
            *(uint32_t*)(sm + OAH + r0 * 144 + c * 2)       = h0;
            *(uint32_t*)(sm + OAL + r0 * 144 + c * 2)       = l0;
            *(uint32_t*)(sm + OAH + (r0 + 8) * 144 + c * 2) = h1;
            *(uint32_t*)(sm + OAL + (r0 + 8) * 144 + c * 2) = l1;
        }
    }
    __syncthreads();

    float acc[2][8][4];
    #pragma unroll
    for (int nt = 0; nt < 8; nt++) {
        float2 bv = *(float2*)&bfs[nt * 8 + cb];
        #pragma unroll
        for (int m = 0; m < 2; m++) {
            acc[m][nt][0] = bv.x; acc[m][nt][1] = bv.y;
            acc[m][nt][2] = bv.x; acc[m][nt][3] = bv.y;
        }
    }
    #pragma unroll
    for (int ks = 0; ks < 4; ks++) {
        const int k0 = ks * 16;
        uint32_t Ah[2][4], Al[2][4];
        #pragma unroll
        for (int mt = 0; mt < 2; mt++) {
            uint32_t ad = sb + OAH + (uint32_t)(t0 + mt * 16 + arow) * 144 + (uint32_t)(k0 * 2 + acol);
            ldm4(Ah[mt][0], Ah[mt][1], Ah[mt][2], Ah[mt][3], ad);
            ldm4(Al[mt][0], Al[mt][1], Al[mt][2], Al[mt][3], ad + (OAL - OAH));
        }
        #pragma unroll
        for (int nt = 0; nt < 8; nt++) {
            const uint32_t boff = (uint32_t)((nt * 8 + (lane >> 2)) * 144 + k0 * 2 + (lane & 3) * 4);
            uint32_t bh0 = *(const uint32_t*)(sm + OWH + boff);
            uint32_t bh1 = *(const uint32_t*)(sm + OWH + boff + 16);
            uint32_t bl0 = *(const uint32_t*)(sm + OWL + boff);
            uint32_t bl1 = *(const uint32_t*)(sm + OWL + boff + 16);
            #pragma unroll
            for (int mt = 0; mt < 2; mt++) {
                mma16816(acc[mt][nt][0], acc[mt][nt][1], acc[mt][nt][2], acc[mt][nt][3],
                         Ah[mt][0], Ah[mt][1], Ah[mt][2], Ah[mt][3], bh0, bh1);
                mma16816(acc[mt][nt][0], acc[mt][nt][1], acc[mt][nt][2], acc[mt][nt][3],
                         Ah[mt][0], Ah[mt][1], Ah[mt][2], Ah[mt][3], bl0, bl1);
                mma16816(acc[mt][nt][0], acc[mt][nt][1], acc[mt][nt][2], acc[mt][nt][3],
                         Al[mt][0], Al[mt][1], Al[mt][2], Al[mt][3], bh0, bh1);
            }
        }
    }

    {
        __half* Gb = g_G + (size_t)b * (G4_ * T_);
        #pragma unroll
        for (int mt = 0; mt < 2; mt++) {
            const int t = t0 + mt * 16 + (lane >> 2);
            #pragma unroll
            for (int nt = 0; nt < 8; nt++) {
                const int c = nt * 8 + cb;
                *(__half2*)&Gb[(size_t)t * 64 + c]       = __floats2half2_rn(acc[mt][nt][0], acc[mt][nt][1]);
                *(__half2*)&Gb[(size_t)(t + 8) * 64 + c] = __floats2half2_rn(acc[mt][nt][2], acc[mt][nt][3]);
            }
        }
    }
}

// ---------------- Phase 2: scan, 2 rows per warp, lane = one hidden unit ----------------
__global__ void __launch_bounds__(128) k_scan(const float* __restrict__ Wf)
{
    __shared__ float sg[4][2][2][8 * SGROW];   // [warp][buf][row][stage]

    const int tid = threadIdx.x, w = tid >> 5, l = tid & 31;
    const int r = l >> 4;            // row within warp
    const int u = l & 15;            // hidden unit
    const int b = blockIdx.x * 8 + w * 2 + r;

    // weights: lane needs (i,g) and (f,o) column pairs for unit u
    u64 wig[16], wfo[16];
    #pragma unroll
    for (int k = 0; k < 16; k++) {
        const float* Wr = Wf + (E_ + k) * G4_;
        wig[k] = pack2(Wr[u],      Wr[u + 16]);
        wfo[k] = pack2(Wr[u + 32], Wr[u + 48]);
    }

    // swizzled gate offsets (col + ((col>>5)<<4))
    const int offI = u;
    const int offG = u + 16;
    const int offF = u + 32 + 16;
    const int offO = u + 48 + 16;

    const __half* GbA = g_G + (size_t)(blockIdx.x * 8 + w * 2)     * (G4_ * T_);
    const __half* GbB = g_G + (size_t)(blockIdx.x * 8 + w * 2 + 1) * (G4_ * T_);

    // staging offsets: lane covers uint4(8 halves) f = l, l+32 of each row
    int soff[2][2];
    #pragma unroll
    for (int k = 0; k < 2; k++) {
        int f  = l + 32 * k;
        int ti = f >> 3;
        int c4a = (f & 7) * 2;
        soff[k][0] = ti * SGROW + c4a * 4 + ((c4a >> 3) << 4);
        int c4b = c4a + 1;
        soff[k][1] = ti * SGROW + c4b * 4 + ((c4b >> 3) << 4);
    }

    float h = 0.f, c = 0.f;

    uint4 rA[2], rB[2];
    // stage group 0 for both rows
    {
        const uint4* sA = (const uint4*)GbA;
        const uint4* sB = (const uint4*)GbB;
        #pragma unroll
        for (int k = 0; k < 2; k++) { rA[k] = sA[l + 32 * k]; rB[k] = sB[l + 32 * k]; }
        #pragma unroll
        for (int k = 0; k < 2; k++) {
            const __half2* pA = (const __half2*)&rA[k];
            const __half2* pB = (const __half2*)&rB[k];
            float2 a0 = __half22float2(pA[0]), a1 = __half22float2(pA[1]);
            float2 a2 = __half22float2(pA[2]), a3 = __half22float2(pA[3]);
            float2 b0 = __half22float2(pB[0]), b1 = __half22float2(pB[1]);
            float2 b2 = __half22float2(pB[2]), b3 = __half22float2(pB[3]);
            *(float4*)&sg[w][0][0][soff[k][0]] = make_float4(a0.x, a0.y, a1.x, a1.y);
            *(float4*)&sg[w][0][0][soff[k][1]] = make_float4(a2.x, a2.y, a3.x, a3.y);
            *(float4*)&sg[w][0][1][soff[k][0]] = make_float4(b0.x, b0.y, b1.x, b1.y);
            *(float4*)&sg[w][0][1][soff[k][1]] = make_float4(b2.x, b2.y, b3.x, b3.y);
        }
    }
    __syncwarp();

    for (int tg = 0; tg < TGRP; ++tg) {
        const int buf = tg & 1;
        if (tg < TGRP - 1) {
            const uint4* sA = (const uint4*)(GbA + (size_t)(tg + 1) * 512);
            const uint4* sB = (const uint4*)(GbB + (size_t)(tg + 1) * 512);
            #pragma unroll
            for (int k = 0; k < 2; k++) { rA[k] = sA[l + 32 * k]; rB[k] = sB[l + 32 * k]; }
        }
        const float* sgr = &sg[w][buf][r][0];
        #pragma unroll
        for (int i = 0; i < 8; i++) {
            float gi = sgr[i * SGROW + offI];
            float gg = sgr[i * SGROW + offG];
            float gf = sgr[i * SGROW + offF];
            float go = sgr[i * SGROW + offO];

            float h0  = __shfl_sync(0xffffffffu, h, 0,  16);
            float h1  = __shfl_sync(0xffffffffu, h, 1,  16);
            float h2  = __shfl_sync(0xffffffffu, h, 2,  16);
            float h3  = __shfl_sync(0xffffffffu, h, 3,  16);
            float h4  = __shfl_sync(0xffffffffu, h, 4,  16);
            float h5  = __shfl_sync(0xffffffffu, h, 5,  16);
            float h6  = __shfl_sync(0xffffffffu, h, 6,  16);
            float h7  = __shfl_sync(0xffffffffu, h, 7,  16);
            float h8  = __shfl_sync(0xffffffffu, h, 8,  16);
            float h9  = __shfl_sync(0xffffffffu, h, 9,  16);
            float h10 = __shfl_sync(0xffffffffu, h, 10, 16);
            float h11 = __shfl_sync(0xffffffffu, h, 11, 16);
            float h12 = __shfl_sync(0xffffffffu, h, 12, 16);
            float h13 = __shfl_sync(0xffffffffu, h, 13, 16);
            float h14 = __shfl_sync(0xffffffffu, h, 14, 16);
            float h15 = __shfl_sync(0xffffffffu, h, 15, 16);

            u64 hp0 = pack2(h0, h0),   hp1 = pack2(h1, h1);
            u64 hp2 = pack2(h2, h2),   hp3 = pack2(h3, h3);
            u64 hp4 = pack2(h4, h4),   hp5 = pack2(h5, h5);
            u64 hp6 = pack2(h6, h6),   hp7 = pack2(h7, h7);
            u64 hp8 = pack2(h8, h8),   hp9 = pack2(h9, h9);
            u64 hp10 = pack2(h10, h10), hp11 = pack2(h11, h11);
            u64 hp12 = pack2(h12, h12), hp13 = pack2(h13, h13);
            u64 hp14 = pack2(h14, h14), hp15 = pack2(h15, h15);

            u64 aig0 = pack2(gi, gg);
            aig0 = fma2(hp0, wig[0],  aig0); aig0 = fma2(hp1, wig[1],  aig0);
            aig0 = fma2(hp2, wig[2],  aig0); aig0 = fma2(hp3, wig[3],  aig0);
            aig0 = fma2(hp4, wig[4],  aig0); aig0 = fma2(hp5, wig[5],  aig0);
            aig0 = fma2(hp6, wig[6],  aig0); aig0 = fma2(hp7, wig[7],  aig0);
            u64 aig1 = fma2(hp8, wig[8], 0ULL); aig1 = fma2(hp9, wig[9],  aig1);
            aig1 = fma2(hp10, wig[10], aig1); aig1 = fma2(hp11, wig[11], aig1);
            aig1 = fma2(hp12, wig[12], aig1); aig1 = fma2(hp13, wig[13], aig1);
            aig1 = fma2(hp14, wig[14], aig1); aig1 = fma2(hp15, wig[15], aig1);
            u64 aig = add2(aig0, aig1);

            u64 afo0 = pack2(gf, go);
            afo0 = fma2(hp0, wfo[0],  afo0); afo0 = fma2(hp1, wfo[1],  afo0);
            afo0 = fma2(hp2, wfo[2],  afo0); afo0 = fma2(hp3, wfo[3],  afo0);
            afo0 = fma2(hp4, wfo[4],  afo0); afo0 = fma2(hp5, wfo[5],  afo0);
            afo0 = fma2(hp6, wfo[6],  afo0); afo0 = fma2(hp7, wfo[7],  afo0);
            u64 afo1 = fma2(hp8, wfo[8], 0ULL); afo1 = fma2(hp9, wfo[9],  afo1);
            afo1 = fma2(hp10, wfo[10], afo1); afo1 = fma2(hp11, wfo[11], afo1);
            afo1 = fma2(hp12, wfo[12], afo1); afo1 = fma2(hp13, wfo[13], afo1);
            afo1 = fma2(hp14, wfo[14], afo1); afo1 = fma2(hp15, wfo[15], afo1);
            u64 afo = add2(afo0, afo1);

            float xi, xg, xf, xo;
            unpack2(aig, xi, xg);
            unpack2(afo, xf, xo);

            float iv = fmaf(0.5f, tanha(0.5f * xi), 0.5f);          // sigmoid(i)
            float gv = tanha(xg);                                   // tanh(g)
            float fv = fmaf(0.5f, tanha(fmaf(0.5f, xf, 0.5f)), 0.5f); // sigmoid(f+1)
            float ov = fmaf(0.5f, tanha(0.5f * xo), 0.5f);          // sigmoid(o)

            c = fmaf(fv, c, iv * gv);
            h = ov * tanha(c);
        }
        if (tg < TGRP - 1) {
            #pragma unroll
            for (int k = 0; k < 2; k++) {
                const __half2* pA = (const __half2*)&rA[k];
                const __half2* pB = (const __half2*)&rB[k];
                float2 a0 = __half22float2(pA[0]), a1 = __half22float2(pA[1]);
                float2 a2 = __half22float2(pA[2]), a3 = __half22float2(pA[3]);
                float2 b0 = __half22float2(pB[0]), b1 = __half22float2(pB[1]);
                float2 b2 = __half22float2(pB[2]), b3 = __half22float2(pB[3]);
                *(float4*)&sg[w][buf ^ 1][0][soff[k][0]] = make_float4(a0.x, a0.y, a1.x, a1.y);
                *(float4*)&sg[w][buf ^ 1][0][soff[k][1]] = make_float4(a2.x, a2.y, a3.x, a3.y);
                *(float4*)&sg[w][buf ^ 1][1][soff[k][0]] = make_float4(b0.x, b0.y, b1.x, b1.y);
                *(float4*)&sg[w][buf ^ 1][1][soff[k][1]] = make_float4(b2.x, b2.y, b3.x, b3.y);
            }
            __syncwarp();
        }
    }
    g_hf[b * H_ + u] = h;
}

// ---------------- Tail (R13-exact, grid 512) ----------------
__global__ void __launch_bounds__(256) k_tail(
    const float* __restrict__ x, const float* __restrict__ W0,
    const float* __restrict__ b0, const float* __restrict__ Wb,
    const float* __restrict__ bb,
    const float* __restrict__ W1, const float* __restrict__ b1,
    const float* __restrict__ W2, const float* __restrict__ b2,
    const float* __restrict__ W3, const float* __restrict__ b3,
    float* __restrict__ out)
{
    __shared__ float W0s[D_ * E_];
    __shared__ float Wbs[E_ * G4_];
    __shared__ float b0s[64], bbs[64];
    __shared__ float W1s[32 * 64], W2s[64 * 16], W3s[32];
    __shared__ float b1s[64], b2s[16], b3s[2];
    __shared__ float xsh[8][20];
    __shared__ __align__(16) float2 hes[8][64];
    __shared__ float hbs[8][16];
    __shared__ float insh[8][32], ush[8][64], vsh[8][16];

    const int tid = threadIdx.x, w = tid >> 5, l = tid & 31;
    const int b = blockIdx.x * 8 + w;

    for (int i = tid; i < D_ * E_;  i += 256) W0s[i] = W0[i];
    for (int i = tid; i < E_ * G4_; i += 256) Wbs[i] = Wb[i];
    for (int i = tid; i < 32 * 64;  i += 256) W1s[i] = W1[i];
    for (int i = tid; i < 64 * 16;  i += 256) W2s[i] = W2[i];
    if (tid < 32) W3s[tid] = W3[tid];
    if (tid < 64) { b0s[tid] = b0[tid]; bbs[tid] = bb[tid]; b1s[tid] = b1[tid]; }
    if (tid < 16) b2s[tid] = b2[tid];
    if (tid < 2)  b3s[tid] = b3[tid];
    __syncthreads();

    if (l < 20) xsh[w][l] = x[((size_t)b * T_ + (T_ - 1)) * D_ + l];
    __syncwarp();

    float a0 = b0s[l], a1 = b0s[l + 32];
    #pragma unroll
    for (int d = 0; d < D_; d++) {
        float xv = xsh[w][d];
        a0 = fmaf(xv, W0s[d * E_ + l],      a0);
        a1 = fmaf(xv, W0s[d * E_ + l + 32], a1);
    }
    a0 = fmaxf(a0, 0.f); a1 = fmaxf(a1, 0.f);
    hes[w][l]      = make_float2(a0, a0);
    hes[w][l + 32] = make_float2(a1, a1);
    __syncwarp();

    const int j = l & 15;
    const int cA = (l < 16) ? l : (32 + j);
    const int cB = cA + 16;
    u64 acc = pack2(bbs[cA], bbs[cB]);
    #pragma unroll 8
    for (int k = 0; k < E_; k++) {
        u64 hd = *(const u64*)&hes[w][k];
        acc = fma2(hd, pack2(Wbs[k * G4_ + cA], Wbs[k * G4_ + cB]), acc);
    }
    float xA, xB; unpack2(acc, xA, xB);

    float bU, kV, aV, bV;
    if (l < 16) { bU = 0.f;  kV = 1.f;  aV = 1.f;  bV = 0.f;  }
    else        { bU = 0.5f; kV = 0.5f; aV = 0.5f; bV = 0.5f; }
    float u = fmaf(0.5f, tanha(fmaf(0.5f, xA, bU)), 0.5f);
    float v = fmaf(aV, tanha(kV * xB), bV);
    float so = __shfl_down_sync(0xffffffffu, v, 16);
    if (l < 16) {
        float cc = u * v;
        hbs[w][l] = so * tanha(cc);
    }
    __syncwarp();

    insh[w][l] = (l < 16) ? g_hf[b * H_ + l] : hbs[w][l - 16];
    __syncwarp();

    float u0 = b1s[l], u1 = b1s[l + 32];
    #pragma unroll 8
    for (int k = 0; k < 32; k++) {
        float t = insh[w][k];
        u0 = fmaf(t, W1s[k * 64 + l],      u0);
        u1 = fmaf(t, W1s[k * 64 + l + 32], u1);
    }
    ush[w][l]      = fmaxf(u0, 0.f);
    ush[w][l + 32] = fmaxf(u1, 0.f);
    __syncwarp();

    if (l < 16) {
        float a = b2s[l];
        #pragma unroll 8
        for (int k = 0; k < 64; k++) a = fmaf(ush[w][k], W2s[k * 16 + l], a);
        vsh[w][l] = fmaxf(a, 0.f);
    }
    __syncwarp();

    if (l < 2) {
        float a = b3s[l];
        #pragma unroll
        for (int k = 0; k < 16; k++) a = fmaf(vsh[w][k], W3s[k * 2 + l], a);
        out[b * 2 + l] = a;
    }
}

extern "C" void kernel_launch(void* const* d_in, const int* in_sizes, int n_in,
                              void* d_out, int out_size)
{
    (void)in_sizes; (void)n_in; (void)out_size;
    const float* x  = (const float*)d_in[0];
    const float* W0 = (const float*)d_in[1];
    const float* b0 = (const float*)d_in[2];
    const float* Wf = (const float*)d_in[3];
    const float* bf = (const float*)d_in[4];
    const float* Wb = (const float*)d_in[5];
    const float* bb = (const float*)d_in[6];
    const float* W1 = (const float*)d_in[7];
    const float* b1 = (const float*)d_in[8];
    const float* W2 = (const float*)d_in[9];
    const float* b2 = (const float*)d_in[10];
    const float* W3 = (const float*)d_in[11];
    const float* b3 = (const float*)d_in[12];
    float* out = (float*)d_out;

    cudaFuncSetAttribute(k_phase1, cudaFuncAttributeMaxDynamicSharedMemorySize, (int)SMEM1);

    k_prep  <<<24, 256>>>(Wf, W0);
    k_phase1<<<B_,     256, SMEM1>>>(x, b0, bf);
    k_scan  <<<B_ / 8, 128>>>(Wf);
    k_tail  <<<B_ / 8, 256>>>(x, W0, b0, Wb, bb, W1, b1, W2, b2, W3, b3, out);
}

// round 16
// speedup vs baseline: 1.7932x; 1.0327x over previous
#include <cuda_runtime.h>
#include <cuda_bf16.h>
#include <cuda_fp16.h>
#include <cstdint>

#define B_  4096
#define T_  256
#define D_  20
#define E_  64
#define H_  16
#define G4_ 64
#define TGRP 32
#define SGROW 80

__device__ __half g_G[(size_t)B_ * G4_ * T_];
__device__ float g_hf[B_ * H_];
__device__ __align__(16) unsigned char g_WfH[9216];
__device__ __align__(16) unsigned char g_WfL[9216];
__device__ __align__(16) unsigned char g_W0H[5120];
__device__ __align__(16) unsigned char g_W0L[5120];

typedef unsigned long long u64;

__device__ __forceinline__ float tanha(float x){ float y; asm("tanh.approx.f32 %0,%1;":"=f"(y):"f"(x)); return y; }
__device__ __forceinline__ u64 pack2(float a,float b){ u64 r; asm("mov.b64 %0,{%1,%2};":"=l"(r):"f"(a),"f"(b)); return r; }
__device__ __forceinline__ void unpack2(u64 v,float&a,float&b){ asm("mov.b64 {%0,%1},%2;":"=f"(a),"=f"(b):"l"(v)); }
__device__ __forceinline__ u64 fma2(u64 a,u64 b,u64 c){ u64 d; asm("fma.rn.f32x2 %0,%1,%2,%3;":"=l"(d):"l"(a),"l"(b),"l"(c)); return d; }
__device__ __forceinline__ u64 add2(u64 a,u64 b){ u64 d; asm("add.rn.f32x2 %0,%1,%2;":"=l"(d):"l"(a),"l"(b)); return d; }
__device__ __forceinline__ uint32_t smem_u32(const void* p){
    uint32_t a; asm("{ .reg .u64 t; cvta.to.shared.u64 t, %1; cvt.u32.u64 %0, t; }":"=r"(a):"l"(p)); return a;
}
__device__ __forceinline__ void mma16816(float& c0, float& c1, float& c2, float& c3,
                                         uint32_t a0, uint32_t a1, uint32_t a2, uint32_t a3,
                                         uint32_t b0, uint32_t b1){
    asm volatile("mma.sync.aligned.m16n8k16.row.col.f32.bf16.bf16.f32 "
        "{%0,%1,%2,%3}, {%4,%5,%6,%7}, {%8,%9}, {%0,%1,%2,%3};"
        : "+f"(c0),"+f"(c1),"+f"(c2),"+f"(c3)
        : "r"(a0),"r"(a1),"r"(a2),"r"(a3),"r"(b0),"r"(b1));
}
__device__ __forceinline__ void ldm4(uint32_t& r0, uint32_t& r1, uint32_t& r2, uint32_t& r3, uint32_t a){
    asm volatile("ldmatrix.sync.aligned.m8n8.x4.shared.b16 {%0,%1,%2,%3}, [%4];"
        : "=r"(r0),"=r"(r1),"=r"(r2),"=r"(r3) : "r"(a));
}
__device__ __forceinline__ void split2(u64 p, uint32_t& hi, uint32_t& lo){
    float v0, v1; unpack2(p, v0, v1);
    v0 = fmaxf(v0, 0.f); v1 = fmaxf(v1, 0.f);
    __nv_bfloat16 h0 = __float2bfloat16(v0), h1 = __float2bfloat16(v1);
    __nv_bfloat16 l0 = __float2bfloat16(v0 - __bfloat162float(h0));
    __nv_bfloat16 l1 = __float2bfloat16(v1 - __bfloat162float(h1));
    hi = (uint32_t)__bfloat16_as_ushort(h0) | ((uint32_t)__bfloat16_as_ushort(h1) << 16);
    lo = (uint32_t)__bfloat16_as_ushort(l0) | ((uint32_t)__bfloat16_as_ushort(l1) << 16);
}
__device__ __forceinline__ void split2nr(float v0, float v1, uint32_t& hi, uint32_t& lo){
    __nv_bfloat16 h0 = __float2bfloat16(v0), h1 = __float2bfloat16(v1);
    __nv_bfloat16 l0 = __float2bfloat16(v0 - __bfloat162float(h0));
    __nv_bfloat16 l1 = __float2bfloat16(v1 - __bfloat162float(h1));
    hi = (uint32_t)__bfloat16_as_ushort(h0) | ((uint32_t)__bfloat16_as_ushort(h1) << 16);
    lo = (uint32_t)__bfloat16_as_ushort(l0) | ((uint32_t)__bfloat16_as_ushort(l1) << 16);
}

#define OAH   0u
#define OAL   36864u
#define OWH   73728u
#define OWL   82944u
#define OW0H  92160u
#define OW0L  97280u
#define OB0   102400u
#define OBF   102656u
#define SMEM1 102912u

// ---------------- Prepack (R13-exact) ----------------
__global__ void k_prep(const float* __restrict__ Wf, const float* __restrict__ W0)
{
    int i = blockIdx.x * 256 + threadIdx.x;
    if (i < 4096) {
        int k = i >> 6, c = i & 63;
        float v = Wf[i];
        __nv_bfloat16 h = __float2bfloat16(v);
        __nv_bfloat16 l = __float2bfloat16(v - __bfloat162float(h));
        *(unsigned short*)(g_WfH + c * 144 + k * 2) = __bfloat16_as_ushort(h);
        *(unsigned short*)(g_WfL + c * 144 + k * 2) = __bfloat16_as_ushort(l);
        if (i < 64) {
            *(uint4*)(g_WfH + i * 144 + 128) = make_uint4(0,0,0,0);
            *(uint4*)(g_WfL + i * 144 + 128) = make_uint4(0,0,0,0);
        }
    }
    int j = i - 4096;
    if (j >= 0 && j < 2048) {
        int k = j >> 6, c = j & 63;
        float v = (k < D_) ? W0[k * 64 + c] : 0.f;
        __nv_bfloat16 h = __float2bfloat16(v);
        __nv_bfloat16 l = __float2bfloat16(v - __bfloat162float(h));
        *(unsigned short*)(g_W0H + c * 80 + k * 2) = __bfloat16_as_ushort(h);
        *(unsigned short*)(g_W0L + c * 80 + k * 2) = __bfloat16_as_ushort(l);
        if (j < 64) {
            *(uint4*)(g_W0H + j * 80 + 64) = make_uint4(0,0,0,0);
            *(uint4*)(g_W0L + j * 80 + 64) = make_uint4(0,0,0,0);
        }
    }
}

// ---------------- Phase 1 (R15 + ldmatrix B fragments) ----------------
__global__ void __launch_bounds__(256, 2) k_phase1(
    const float* __restrict__ x, const float* __restrict__ b0,
    const float* __restrict__ bf)
{
    extern __shared__ char sm[];
    const uint32_t sb = smem_u32(sm);
    float* b0s = (float*)(sm + OB0);
    float* bfs = (float*)(sm + OBF);

    const int tid = threadIdx.x, wid = tid >> 5, lane = tid & 31;
    const int b = blockIdx.x;

    if (tid < 64) { b0s[tid] = b0[tid]; bfs[tid] = bf[tid]; }
    {
        const uint4* srcH = (const uint4*)g_WfH;
        const uint4* srcL = (const uint4*)g_WfL;
        #pragma unroll
        for (int q = 0; q < 3; q++) {
            int i = tid + q * 256;
            if (i < 576) {
                *(uint4*)(sm + OWH + i * 16) = srcH[i];
                *(uint4*)(sm + OWL + i * 16) = srcL[i];
            }
        }
        const uint4* s0H = (const uint4*)g_W0H;
        const uint4* s0L = (const uint4*)g_W0L;
        #pragma unroll
        for (int q = 0; q < 2; q++) {
            int i = tid + q * 256;
            if (i < 320) {
                *(uint4*)(sm + OW0H + i * 16) = s0H[i];
                *(uint4*)(sm + OW0L + i * 16) = s0L[i];
            }
        }
    }

    {
        const int t = tid;
        const float4* xp4 = (const float4*)(x + (size_t)b * (T_ * D_) + t * D_);
        float xv[20];
        #pragma unroll
        for (int q = 0; q < 5; q++) {
            float4 f = __ldg(xp4 + q);
            xv[4*q] = f.x; xv[4*q+1] = f.y; xv[4*q+2] = f.z; xv[4*q+3] = f.w;
        }
        uint32_t hw[16], lw[16];
        #pragma unroll
        for (int p = 0; p < 10; p++) split2nr(xv[2*p], xv[2*p+1], hw[p], lw[p]);
        #pragma unroll
        for (int p = 10; p < 16; p++) { hw[p] = 0u; lw[p] = 0u; }
        #pragma unroll
        for (int q = 0; q < 4; q++) {
            *(uint4*)(sm + OAH + t * 144 + q * 16) = make_uint4(hw[4*q], hw[4*q+1], hw[4*q+2], hw[4*q+3]);
            *(uint4*)(sm + OAL + t * 144 + q * 16) = make_uint4(lw[4*q], lw[4*q+1], lw[4*q+2], lw[4*q+3]);
        }
    }
    __syncthreads();

    const int t0 = wid * 32;
    const int arow = ((lane >> 3) & 1) * 8 + (lane & 7);
    const int acol = (lane >> 4) * 16;
    const int cb = (lane & 3) * 2;
    // B-fragment ldmatrix addressing (R8-verified): seg 0..3 of the warp
    const int seg  = lane >> 3;
    const int brow = (lane & 7) + ((seg & 2) ? 8 : 0);
    const int bkof = (seg & 1) ? 16 : 0;

    // ---- GEMM1 ----
    float acc1[2][8][4];
    #pragma unroll
    for (int nt = 0; nt < 8; nt++) {
        float2 bv = *(float2*)&b0s[nt * 8 + cb];
        #pragma unroll
        for (int m = 0; m < 2; m++) {
            acc1[m][nt][0] = bv.x; acc1[m][nt][1] = bv.y;
            acc1[m][nt][2] = bv.x; acc1[m][nt][3] = bv.y;
        }
    }
    #pragma unroll
    for (int ks = 0; ks < 2; ks++) {
        const int k0 = ks * 16;
        uint32_t Ah[2][4], Al[2][4];
        #pragma unroll
        for (int mt = 0; mt < 2; mt++) {
            uint32_t ad = sb + OAH + (uint32_t)(t0 + mt * 16 + arow) * 144 + (uint32_t)(k0 * 2 + acol);
            ldm4(Ah[mt][0], Ah[mt][1], Ah[mt][2], Ah[mt][3], ad);
            ldm4(Al[mt][0], Al[mt][1], Al[mt][2], Al[mt][3], ad + (OAL - OAH));
        }
        #pragma unroll
        for (int p = 0; p < 4; p++) {
            uint32_t badr = sb + OW0H + (uint32_t)(p * 16 + brow) * 80 + (uint32_t)(k0 * 2 + bkof);
            uint32_t bh0, bh1, bh2, bh3, bl0, bl1, bl2, bl3;
            ldm4(bh0, bh1, bh2, bh3, badr);
            ldm4(bl0, bl1, bl2, bl3, badr + (OW0L - OW0H));
            #pragma unroll
            for (int mt = 0; mt < 2; mt++) {
                mma16816(acc1[mt][2*p][0], acc1[mt][2*p][1], acc1[mt][2*p][2], acc1[mt][2*p][3],
                         Ah[mt][0], Ah[mt][1], Ah[mt][2], Ah[mt][3], bh0, bh1);
                mma16816(acc1[mt][2*p][0], acc1[mt][2*p][1], acc1[mt][2*p][2], acc1[mt][2*p][3],
                         Ah[mt][0], Ah[mt][1], Ah[mt][2], Ah[mt][3], bl0, bl1);
                mma16816(acc1[mt][2*p][0], acc1[mt][2*p][1], acc1[mt][2*p][2], acc1[mt][2*p][3],
                         Al[mt][0], Al[mt][1], Al[mt][2], Al[mt][3], bh0, bh1);
                mma16816(acc1[mt][2*p+1][0], acc1[mt][2*p+1][1], acc1[mt][2*p+1][2], acc1[mt][2*p+1][3],
                         Ah[mt][0], Ah[mt][1], Ah[mt][2], Ah[mt][3], bh2, bh3);
                mma16816(acc1[mt][2*p+1][0], acc1[mt][2*p+1][1], acc1[mt][2*p+1][2], acc1[mt][2*p+1][3],
                         Ah[mt][0], Ah[mt][1], Ah[mt][2], Ah[mt][3], bl2, bl3);
                mma16816(acc1[mt][2*p+1][0], acc1[mt][2*p+1][1], acc1[mt][2*p+1][2], acc1[mt][2*p+1][3],
                         Al[mt][0], Al[mt][1], Al[mt][2], Al[mt][3], bh2, bh3);
            }
        }
    }
    __syncthreads();

    #pragma unroll
    for (int mt = 0; mt < 2; mt++) {
        const int r0 = t0 + mt * 16 + (lane >> 2);
        #pragma unroll
        for (int nt = 0; nt < 8; nt++) {
            const int c = nt * 8 + cb;
            uint32_t h0, l0, h1, l1;
            split2(pack2(acc1[mt][nt][0], acc1[mt][nt][1]), h0, l0);
            split2(pack2(acc1[mt][nt][2], acc1[mt][nt][3]), h1, l1);
            *(uint32_t*)(sm + OAH + r0 * 144 + c * 2)       = h0;
            *(uint32_t*)(sm + OAL + r0 * 144 + c * 2)       = l0;
            *(uint32_t*)(sm + OAH + (r0 + 8) * 144 + c * 2) = h1;
            *(uint32_t*)(sm + OAL + (r0 + 8) * 144 + c * 2) = l1;
        }
    }
    __syncthreads();

    // ---- GEMM2 ----
    float acc[2][8][4];
    #pragma unroll
    for (int nt = 0; nt < 8; nt++) {
        float2 bv = *(float2*)&bfs[nt * 8 + cb];
        #pragma unroll
        for (int m = 0; m < 2; m++) {
            acc[m][nt][0] = bv.x; acc[m][nt][1] = bv.y;
            acc[m][nt][2] = bv.x; acc[m][nt][3] = bv.y;
        }
    }
    #pragma unroll
    for (int ks = 0; ks < 4; ks++) {
        const int k0 = ks * 16;
        uint32_t Ah[2][4], Al[2][4];
        #pragma unroll
        for (int mt = 0; mt < 2; mt++) {
            uint32_t ad = sb + OAH + (uint32_t)(t0 + mt * 16 + arow) * 144 + (uint32_t)(k0 * 2 + acol);
            ldm4(Ah[mt][0], Ah[mt][1], Ah[mt][2], Ah[mt][3], ad);
            ldm4(Al[mt][0], Al[mt][1], Al[mt][2], Al[mt][3], ad + (OAL - OAH));
        }
        #pragma unroll
        for (int p = 0; p < 4; p++) {
            uint32_t badr = sb + OWH + (uint32_t)(p * 16 + brow) * 144 + (uint32_t)(k0 * 2 + bkof);
            uint32_t bh0, bh1, bh2, bh3, bl0, bl1, bl2, bl3;
            ldm4(bh0, bh1, bh2, bh3, badr);
            ldm4(bl0, bl1, bl2, bl3, badr + (OWL - OWH));
            #pragma unroll
            for (int mt = 0; mt < 2; mt++) {
                mma16816(acc[mt][2*p][0], acc[mt][2*p][1], acc[mt][2*p][2], acc[mt][2*p][3],
                         Ah[mt][0], Ah[mt][1], Ah[mt][2], Ah[mt][3], bh0, bh1);
                mma16816(acc[mt][2*p][0], acc[mt][2*p][1], acc[mt][2*p][2], acc[mt][2*p][3],
                         Ah[mt][0], Ah[mt][1], Ah[mt][2], Ah[mt][3], bl0, bl1);
                mma16816(acc[mt][2*p][0], acc[mt][2*p][1], acc[mt][2*p][2], acc[mt][2*p][3],
                         Al[mt][0], Al[mt][1], Al[mt][2], Al[mt][3], bh0, bh1);
                mma16816(acc[mt][2*p+1][0], acc[mt][2*p+1][1], acc[mt][2*p+1][2], acc[mt][2*p+1][3],
                         Ah[mt][0], Ah[mt][1], Ah[mt][2], Ah[mt][3], bh2, bh3);
                mma16816(acc[mt][2*p+1][0], acc[mt][2*p+1][1], acc[mt][2*p+1][2], acc[mt][2*p+1][3],
                         Ah[mt][0], Ah[mt][1], Ah[mt][2], Ah[mt][3], bl2, bl3);
                mma16816(acc[mt][2*p+1][0], acc[mt][2*p+1][1], acc[mt][2*p+1][2], acc[mt][2*p+1][3],
                         Al[mt][0], Al[mt][1], Al[mt][2], Al[mt][3], bh2, bh3);
            }
        }
    }

    {
        __half* Gb = g_G + (size_t)b * (G4_ * T_);
        #pragma unroll
        for (int mt = 0; mt < 2; mt++) {
            const int t = t0 + mt * 16 + (lane >> 2);
            #pragma unroll
            for (int nt = 0; nt < 8; nt++) {
                const int c = nt * 8 + cb;
                *(__half2*)&Gb[(size_t)t * 64 + c]       = __floats2half2_rn(acc[mt][nt][0], acc[mt][nt][1]);
                *(__half2*)&Gb[(size_t)(t + 8) * 64 + c] = __floats2half2_rn(acc[mt][nt][2], acc[mt][nt][3]);
            }
        }
    }
}

// ---------------- Phase 2: scan (R15 + depth-2 prefetch) ----------------
__global__ void __launch_bounds__(128) k_scan(const float* __restrict__ Wf)
{
    __shared__ float sg[4][2][2][8 * SGROW];

    const int tid = threadIdx.x, w = tid >> 5, l = tid & 31;
    const int r = l >> 4;
    const int u = l & 15;
    const int b = blockIdx.x * 8 + w * 2 + r;

    u64 wig[16], wfo[16];
    #pragma unroll
    for (int k = 0; k < 16; k++) {
        const float* Wr = Wf + (E_ + k) * G4_;
        wig[k] = pack2(Wr[u],      Wr[u + 16]);
        wfo[k] = pack2(Wr[u + 32], Wr[u + 48]);
    }

    const int offI = u;
    const int offG = u + 16;
    const int offF = u + 32 + 16;
    const int offO = u + 48 + 16;

    const __half* GbA = g_G + (size_t)(blockIdx.x * 8 + w * 2)     * (G4_ * T_);
    const __half* GbB = g_G + (size_t)(blockIdx.x * 8 + w * 2 + 1) * (G4_ * T_);

    int soff[2][2];
    #pragma unroll
    for (int k = 0; k < 2; k++) {
        int f  = l + 32 * k;
        int ti = f >> 3;
        int c4a = (f & 7) * 2;
        soff[k][0] = ti * SGROW + c4a * 4 + ((c4a >> 3) << 4);
        int c4b = c4a + 1;
        soff[k][1] = ti * SGROW + c4b * 4 + ((c4b >> 3) << 4);
    }

    float h = 0.f, c = 0.f;

    uint4 rA[2][2], rB[2][2];   // [set][k]

    // prologue: stage G0, have G1 in set1, G2 in set0
    {
        const uint4* sA = (const uint4*)GbA;
        const uint4* sB = (const uint4*)GbB;
        #pragma unroll
        for (int k = 0; k < 2; k++) { rA[0][k] = sA[l + 32 * k]; rB[0][k] = sB[l + 32 * k]; }
        #pragma unroll
        for (int k = 0; k < 2; k++) {
            const __half2* pA = (const __half2*)&rA[0][k];
            const __half2* pB = (const __half2*)&rB[0][k];
            float2 a0 = __half22float2(pA[0]), a1 = __half22float2(pA[1]);
            float2 a2 = __half22float2(pA[2]), a3 = __half22float2(pA[3]);
            float2 b0 = __half22float2(pB[0]), b1 = __half22float2(pB[1]);
            float2 b2 = __half22float2(pB[2]), b3 = __half22float2(pB[3]);
            *(float4*)&sg[w][0][0][soff[k][0]] = make_float4(a0.x, a0.y, a1.x, a1.y);
            *(float4*)&sg[w][0][0][soff[k][1]] = make_float4(a2.x, a2.y, a3.x, a3.y);
            *(float4*)&sg[w][0][1][soff[k][0]] = make_float4(b0.x, b0.y, b1.x, b1.y);
            *(float4*)&sg[w][0][1][soff[k][1]] = make_float4(b2.x, b2.y, b3.x, b3.y);
        }
        const uint4* sA1 = (const uint4*)(GbA + 512);
        const uint4* sB1 = (const uint4*)(GbB + 512);
        #pragma unroll
        for (int k = 0; k < 2; k++) { rA[1][k] = sA1[l + 32 * k]; rB[1][k] = sB1[l + 32 * k]; }
        const uint4* sA2 = (const uint4*)(GbA + 1024);
        const uint4* sB2 = (const uint4*)(GbB + 1024);
        #pragma unroll
        for (int k = 0; k < 2; k++) { rA[0][k] = sA2[l + 32 * k]; rB[0][k] = sB2[l + 32 * k]; }
    }
    __syncwarp();

    for (int tg = 0; tg < TGRP; ++tg) {
        const int buf = tg & 1;
        const float* sgr = &sg[w][buf][r][0];
        #pragma unroll
        for (int i = 0; i < 8; i++) {
            float gi = sgr[i * SGROW + offI];
            float gg = sgr[i * SGROW + offG];
            float gf = sgr[i * SGROW + offF];
            float go = sgr[i * SGROW + offO];

            float h0  = __shfl_sync(0xffffffffu, h, 0,  16);
            float h1  = __shfl_sync(0xffffffffu, h, 1,  16);
            float h2  = __shfl_sync(0xffffffffu, h, 2,  16);
            float h3  = __shfl_sync(0xffffffffu, h, 3,  16);
            float h4  = __shfl_sync(0xffffffffu, h, 4,  16);
            float h5  = __shfl_sync(0xffffffffu, h, 5,  16);
            float h6  = __shfl_sync(0xffffffffu, h, 6,  16);
            float h7  = __shfl_sync(0xffffffffu, h, 7,  16);
            float h8  = __shfl_sync(0xffffffffu, h, 8,  16);
            float h9  = __shfl_sync(0xffffffffu, h, 9,  16);
            float h10 = __shfl_sync(0xffffffffu, h, 10, 16);
            float h11 = __shfl_sync(0xffffffffu, h, 11, 16);
            float h12 = __shfl_sync(0xffffffffu, h, 12, 16);
            float h13 = __shfl_sync(0xffffffffu, h, 13, 16);
            float h14 = __shfl_sync(0xffffffffu, h, 14, 16);
            float h15 = __shfl_sync(0xffffffffu, h, 15, 16);

            u64 hp0 = pack2(h0, h0),   hp1 = pack2(h1, h1);
            u64 hp2 = pack2(h2, h2),   hp3 = pack2(h3, h3);
            u64 hp4 = pack2(h4, h4),   hp5 = pack2(h5, h5);
            u64 hp6 = pack2(h6, h6),   hp7 = pack2(h7, h7);
            u64 hp8 = pack2(h8, h8),   hp9 = pack2(h9, h9);
            u64 hp10 = pack2(h10, h10), hp11 = pack2(h11, h11);
            u64 hp12 = pack2(h12, h12), hp13 = pack2(h13, h13);
            u64 hp14 = pack2(h14, h14), hp15 = pack2(h15, h15);

            u64 aig0 = pack2(gi, gg);
            aig0 = fma2(hp0, wig[0],  aig0); aig0 = fma2(hp1, wig[1],  aig0);
            aig0 = fma2(hp2, wig[2],  aig0); aig0 = fma2(hp3, wig[3],  aig0);
            aig0 = fma2(hp4, wig[4],  aig0); aig0 = fma2(hp5, wig[5],  aig0);
            aig0 = fma2(hp6, wig[6],  aig0); aig0 = fma2(hp7, wig[7],  aig0);
            u64 aig1 = fma2(hp8, wig[8], 0ULL); aig1 = fma2(hp9, wig[9],  aig1);
            aig1 = fma2(hp10, wig[10], aig1); aig1 = fma2(hp11, wig[11], aig1);
            aig1 = fma2(hp12, wig[12], aig1); aig1 = fma2(hp13, wig[13], aig1);
            aig1 = fma2(hp14, wig[14], aig1); aig1 = fma2(hp15, wig[15], aig1);
            u64 aig = add2(aig0, aig1);

            u64 afo0 = pack2(gf, go);
            afo0 = fma2(hp0, wfo[0],  afo0); afo0 = fma2(hp1, wfo[1],  afo0);
            afo0 = fma2(hp2, wfo[2],  afo0); afo0 = fma2(hp3, wfo[3],  afo0);
            afo0 = fma2(hp4, wfo[4],  afo0); afo0 = fma2(hp5, wfo[5],  afo0);
            afo0 = fma2(hp6, wfo[6],  afo0); afo0 = fma2(hp7, wfo[7],  afo0);
            u64 afo1 = fma2(hp8, wfo[8], 0ULL); afo1 = fma2(hp9, wfo[9],  afo1);
            afo1 = fma2(hp10, wfo[10], afo1); afo1 = fma2(hp11, wfo[11], afo1);
            afo1 = fma2(hp12, wfo[12], afo1); afo1 = fma2(hp13, wfo[13], afo1);
            afo1 = fma2(hp14, wfo[14], afo1); afo1 = fma2(hp15, wfo[15], afo1);
            u64 afo = add2(afo0, afo1);

            float xi, xg, xf, xo;
            unpack2(aig, xi, xg);
            unpack2(afo, xf, xo);

            float iv = fmaf(0.5f, tanha(0.5f * xi), 0.5f);
            float gv = tanha(xg);
            float fv = fmaf(0.5f, tanha(fmaf(0.5f, xf, 0.5f)), 0.5f);
            float ov = fmaf(0.5f, tanha(0.5f * xo), 0.5f);

            c = fmaf(fv, c, iv * gv);
            h = ov * tanha(c);
        }
        if (tg < TGRP - 1) {
            const int ns = (tg + 1) & 1;    // set holding G[tg+1]
            #pragma unroll
            for (int k = 0; k < 2; k++) {
                const __half2* pA = (const __half2*)&rA[ns][k];
                const __half2* pB = (const __half2*)&rB[ns][k];
                float2 a0 = __half22float2(pA[0]), a1 = __half22float2(pA[1]);
                float2 a2 = __half22float2(pA[2]), a3 = __half22float2(pA[3]);
                float2 b0 = __half22float2(pB[0]), b1 = __half22float2(pB[1]);
                float2 b2 = __half22float2(pB[2]), b3 = __half22float2(pB[3]);
                *(float4*)&sg[w][buf ^ 1][0][soff[k][0]] = make_float4(a0.x, a0.y, a1.x, a1.y);
                *(float4*)&sg[w][buf ^ 1][0][soff[k][1]] = make_float4(a2.x, a2.y, a3.x, a3.y);
                *(float4*)&sg[w][buf ^ 1][1][soff[k][0]] = make_float4(b0.x, b0.y, b1.x, b1.y);
                *(float4*)&sg[w][buf ^ 1][1][soff[k][1]] = make_float4(b2.x, b2.y, b3.x, b3.y);
            }
            if (tg + 3 < TGRP) {            // refill freed set with G[tg+3]
                const uint4* sA = (const uint4*)(GbA + (size_t)(tg + 3) * 512);
                const uint4* sB = (const uint4*)(GbB + (size_t)(tg + 3) * 512);
                #pragma unroll
                for (int k = 0; k < 2; k++) { rA[ns][k] = sA[l + 32 * k]; rB[ns][k] = sB[l + 32 * k]; }
            }
            __syncwarp();
        }
    }
    g_hf[b * H_ + u] = h;
}

// ---------------- Tail (R15-exact) ----------------
__global__ void __launch_bounds__(256) k_tail(
    const float* __restrict__ x, const float* __restrict__ W0,
    const float* __restrict__ b0, const float* __restrict__ Wb,
    const float* __restrict__ bb,
    const float* __restrict__ W1, const float* __restrict__ b1,
    const float* __restrict__ W2, const float* __restrict__ b2,
    const float* __restrict__ W3, const float* __restrict__ b3,
    float* __restrict__ out)
{
    __shared__ float W0s[D_ * E_];
    __shared__ float Wbs[E_ * G4_];
    __shared__ float b0s[64], bbs[64];
    __shared__ float W1s[32 * 64], W2s[64 * 16], W3s[32];
    __shared__ float b1s[64], b2s[16], b3s[2];
    __shared__ float xsh[8][20];
    __shared__ __align__(16) float2 hes[8][64];
    __shared__ float hbs[8][16];
    __shared__ float insh[8][32], ush[8][64], vsh[8][16];

    const int tid = threadIdx.x, w = tid >> 5, l = tid & 31;
    const int b = blockIdx.x * 8 + w;

    for (int i = tid; i < D_ * E_;  i += 256) W0s[i] = W0[i];
    for (int i = tid; i < E_ * G4_; i += 256) Wbs[i] = Wb[i];
    for (int i = tid; i < 32 * 64;  i += 256) W1s[i] = W1[i];
    for (int i = tid; i < 64 * 16;  i += 256) W2s[i] = W2[i];
    if (tid < 32) W3s[tid] = W3[tid];
    if (tid < 64) { b0s[tid] = b0[tid]; bbs[tid] = bb[tid]; b1s[tid] = b1[tid]; }
    if (tid < 16) b2s[tid] = b2[tid];
    if (tid < 2)  b3s[tid] = b3[tid];
    __syncthreads();

    if (l < 20) xsh[w][l] = x[((size_t)b * T_ + (T_ - 1)) * D_ + l];
    __syncwarp();

    float a0 = b0s[l], a1 = b0s[l + 32];
    #pragma unroll
    for (int d = 0; d < D_; d++) {
        float xv = xsh[w][d];
        a0 = fmaf(xv, W0s[d * E_ + l],      a0);
        a1 = fmaf(xv, W0s[d * E_ + l + 32], a1);
    }
    a0 = fmaxf(a0, 0.f); a1 = fmaxf(a1, 0.f);
    hes[w][l]      = make_float2(a0, a0);
    hes[w][l + 32] = make_float2(a1, a1);
    __syncwarp();

    const int j = l & 15;
    const int cA = (l < 16) ? l : (32 + j);
    const int cB = cA + 16;
    u64 acc = pack2(bbs[cA], bbs[cB]);
    #pragma unroll 8
    for (int k = 0; k < E_; k++) {
        u64 hd = *(const u64*)&hes[w][k];
        acc = fma2(hd, pack2(Wbs[k * G4_ + cA], Wbs[k * G4_ + cB]), acc);
    }
    float xA, xB; unpack2(acc, xA, xB);

    float bU, kV, aV, bV;
    if (l < 16) { bU = 0.f;  kV = 1.f;  aV = 1.f;  bV = 0.f;  }
    else        { bU = 0.5f; kV = 0.5f; aV = 0.5f; bV = 0.5f; }
    float u = fmaf(0.5f, tanha(fmaf(0.5f, xA, bU)), 0.5f);
    float v = fmaf(aV, tanha(kV * xB), bV);
    float so = __shfl_down_sync(0xffffffffu, v, 16);
    if (l < 16) {
        float cc = u * v;
        hbs[w][l] = so * tanha(cc);
    }
    __syncwarp();

    insh[w][l] = (l < 16) ? g_hf[b * H_ + l] : hbs[w][l - 16];
    __syncwarp();

    float u0 = b1s[l], u1 = b1s[l + 32];
    #pragma unroll 8
    for (int k = 0; k < 32; k++) {
        float t = insh[w][k];
        u0 = fmaf(t, W1s[k * 64 + l],      u0);
        u1 = fmaf(t, W1s[k * 64 + l + 32], u1);
    }
    ush[w][l]      = fmaxf(u0, 0.f);
    ush[w][l + 32] = fmaxf(u1, 0.f);
    __syncwarp();

    if (l < 16) {
        float a = b2s[l];
        #pragma unroll 8
        for (int k = 0; k < 64; k++) a = fmaf(ush[w][k], W2s[k * 16 + l], a);
        vsh[w][l] = fmaxf(a, 0.f);
    }
    __syncwarp();

    if (l < 2) {
        float a = b3s[l];
        #pragma unroll
        for (int k = 0; k < 16; k++) a = fmaf(vsh[w][k], W3s[k * 2 + l], a);
        out[b * 2 + l] = a;
    }
}

extern "C" void kernel_launch(void* const* d_in, const int* in_sizes, int n_in,
                              void* d_out, int out_size)
{
    (void)in_sizes; (void)n_in; (void)out_size;
    const float* x  = (const float*)d_in[0];
    const float* W0 = (const float*)d_in[1];
    const float* b0 = (const float*)d_in[2];
    const float* Wf = (const float*)d_in[3];
    const float* bf = (const float*)d_in[4];
    const float* Wb = (const float*)d_in[5];
    const float* bb = (const float*)d_in[6];
    const float* W1 = (const float*)d_in[7];
    const float* b1 = (const float*)d_in[8];
    const float* W2 = (const float*)d_in[9];
    const float* b2 = (const float*)d_in[10];
    const float* W3 = (const float*)d_in[11];
    const float* b3 = (const float*)d_in[12];
    float* out = (float*)d_out;

    cudaFuncSetAttribute(k_phase1, cudaFuncAttributeMaxDynamicSharedMemorySize, (int)SMEM1);

    k_prep  <<<24, 256>>>(Wf, W0);
    k_phase1<<<B_,     256, SMEM1>>>(x, b0, bf);
    k_scan  <<<B_ / 8, 128>>>(Wf);
    k_tail  <<<B_ / 8, 256>>>(x, W0, b0, Wb, bb, W1, b1, W2, b2, W3, b3, out);
}